// round 16
// baseline (speedup 1.0000x reference)
#include <cuda_runtime.h>
#include <cuda_bf16.h>

// VolumeSDF renderer: one warp per ray, tail-split march.
//   Phase 1: samples 0..95 on lanes 0..23 (4 samples/lane, float4 loads).
//   Phase 2: samples 96..127, 1/lane -- run ONLY if cum96 < SKIP2 (the tail
//   weight telescopes to <= 2^-cum96). cum96 averages ~10.8 nats vs the
//   7-nat gate, so ~85-90% of warps skip phase 2 entirely: saves ~12 MB of
//   sdf/depth with no second memory exposure for most warps (this is why
//   R10's 64/64 split failed and this 96/32 split should not).
//
//   density = ALPHA * LaplaceCDF(-sdf; BETA)
//   tau_s   = density_s * delta_s,  delta = diff(depth), last = 1e10
//   T_s     = exp(-inclusive_cumsum(tau)_s);  w_s = T_s*(1-exp(-tau_s+eps))
//   out[n]  = sum_s w_s * color[n,s,:]
//
// All exponentials base-2 (ex2.approx), cumsum carried in log2-units.
// Color gating: lanes 0-15 unconditional (front-batched); lanes 16-23 and
// all phase-2 lanes gate on their scan prefix vs SKIP2 (7.0 nats; R13/R14
// calibration: rel_err ~2.4e-4, 4x under the 1e-3 gate).

#define FAR_DELTA 1e10f
#define AEXP   28.853900817779268f   // (1/BETA)*log2(e) = 20*1.442695
#define DENS2  14.426950408889634f   // ALPHA*log2(e)
#define EPS2   1.442695041e-10f      // EPS*log2(e)
#define SKIP2  10.098865286222745f   // 7.0 nats in bits
#define EARLY_LANES 16

__device__ __forceinline__ float ex2(float x) {
    float y;
    asm("ex2.approx.ftz.f32 %0, %1;" : "=f"(y) : "f"(x));
    return y;
}

// tau per unit delta, in base-2 units: DENS2 * LaplaceCDF(-x, BETA)
__device__ __forceinline__ float dens2(float x) {
    const float e = 0.5f * ex2(-fabsf(x) * AEXP);
    const float cdf = (x > 0.0f) ? e : (1.0f - e);
    return DENS2 * cdf;
}

__global__ __launch_bounds__(256)
void volume_sdf_render_kernel(const float* __restrict__ sdf,
                              const float* __restrict__ color,
                              const float* __restrict__ depth,
                              float* __restrict__ out,
                              int N)
{
    const int gtid = blockIdx.x * blockDim.x + threadIdx.x;
    const int ray  = gtid >> 5;          // one warp per ray
    const int lane = threadIdx.x & 31;
    if (ray >= N) return;

    const int S = 128;
    const long long rbase = (long long)ray * S;
    const long long base  = rbase + lane * 4;     // phase-1 samples (lanes 0-23)
    const long long cbase = base * 3;
    const bool active = (lane < 24);
    const bool early  = (lane < EARLY_LANES);

    // ---- Phase-1 front-batched loads ----
    float4 s4 = make_float4(0.f, 0.f, 0.f, 0.f);
    float4 d4 = make_float4(0.f, 0.f, 0.f, 0.f);
    if (active) {
        s4 = *reinterpret_cast<const float4*>(sdf   + base);
        d4 = *reinterpret_cast<const float4*>(depth + base);
    }
    float4 ca, cb, cc;
    if (early) {
        ca = *reinterpret_cast<const float4*>(color + cbase);
        cb = *reinterpret_cast<const float4*>(color + cbase + 4);
        cc = *reinterpret_cast<const float4*>(color + cbase + 8);
    }
    // Broadcast depth[96] (uniform address -> single sector) for lane 23's delta.
    const float d96 = __ldg(depth + rbase + 96);

    // Deltas. depth[4l+4] lives in the next lane's d4.x; lane 23 uses d96.
    const float dnext = __shfl_down_sync(0xffffffffu, d4.x, 1);
    float del[4];
    del[0] = d4.y - d4.x;
    del[1] = d4.z - d4.y;
    del[2] = d4.w - d4.z;
    del[3] = ((lane == 23) ? d96 : dnext) - d4.w;

    const float sd[4] = {s4.x, s4.y, s4.z, s4.w};

    // tau in base-2 units; u_i = 2^(-tau2_i + eps2) = 1 - trans_i.
    float tau[4], u[4];
#pragma unroll
    for (int i = 0; i < 4; ++i) {
        tau[i] = active ? (dens2(sd[i]) * del[i]) : 0.0f;
        u[i]   = ex2(-tau[i] + EPS2);
    }

    // Per-lane inclusive cumsum (base-2 units).
    const float c0 = tau[0];
    const float c1 = c0 + tau[1];
    const float c2 = c1 + tau[2];
    const float c3 = c2 + tau[3];

    // Warp inclusive scan of lane totals (lanes 24-31 contribute 0).
    float incl = c3;
#pragma unroll
    for (int off = 1; off < 32; off <<= 1) {
        const float v = __shfl_up_sync(0xffffffffu, incl, off);
        if (lane >= off) incl += v;
    }
    // Exclusive prefix from the PREVIOUS lane's inclusive value. Never by
    // subtraction (catastrophic cancellation -- R1/R2 bug).
    float prefix = __shfl_up_sync(0xffffffffu, incl, 1);
    if (lane == 0) prefix = 0.0f;
    const float cum96 = __shfl_sync(0xffffffffu, incl, 31);

    // Gated phase-1 color (lanes 16-23).
    const bool have = active && (early || (prefix < SKIP2));
    if (have && !early) {
        ca = *reinterpret_cast<const float4*>(color + cbase);
        cb = *reinterpret_cast<const float4*>(color + cbase + 4);
        cc = *reinterpret_cast<const float4*>(color + cbase + 8);
    }

    float r = 0.0f, g = 0.0f, b = 0.0f;
    if (have) {
        // Telescoping transmittance: one EX2 total.
        const float T0 = ex2(-(prefix + c0));
        const float T1 = T0 * u[1];
        const float T2 = T1 * u[2];
        const float T3 = T2 * u[3];
        const float w0 = T0 * (1.0f - u[0]);
        const float w1 = T1 * (1.0f - u[1]);
        const float w2 = T2 * (1.0f - u[2]);
        const float w3 = T3 * (1.0f - u[3]);

        // sample0=(ca.x,ca.y,ca.z) sample1=(ca.w,cb.x,cb.y)
        // sample2=(cb.z,cb.w,cc.x) sample3=(cc.y,cc.z,cc.w)
        r = w0 * ca.x + w1 * ca.w + w2 * cb.z + w3 * cc.y;
        g = w0 * ca.y + w1 * cb.x + w2 * cb.w + w3 * cc.z;
        b = w0 * ca.z + w1 * cb.y + w2 * cc.x + w3 * cc.w;
    }

    // ---- Phase 2 (samples 96-127), warp-uniform skip ----
    if (cum96 < SKIP2) {
        const long long idx = rbase + 96 + lane;   // 1 sample per lane
        const float sv = sdf[idx];
        const float dv = depth[idx];
        const float dn = __shfl_down_sync(0xffffffffu, dv, 1);
        const float delta = (lane == 31) ? FAR_DELTA : (dn - dv);
        const float t2 = dens2(sv) * delta;

        float incl2 = t2;
#pragma unroll
        for (int off = 1; off < 32; off <<= 1) {
            const float v = __shfl_up_sync(0xffffffffu, incl2, off);
            if (lane >= off) incl2 += v;
        }
        float pre2 = __shfl_up_sync(0xffffffffu, incl2, 1);
        if (lane == 0) pre2 = 0.0f;
        pre2 += cum96;

        if (pre2 < SKIP2) {
            const float* cp = color + idx * 3;
            const float uu = ex2(-t2 + EPS2);
            const float w  = ex2(-(pre2 + t2)) * (1.0f - uu);
            r += w * cp[0];
            g += w * cp[1];
            b += w * cp[2];
        }
    }

    // Warp reduction over lanes (samples).
#pragma unroll
    for (int off = 16; off > 0; off >>= 1) {
        r += __shfl_xor_sync(0xffffffffu, r, off);
        g += __shfl_xor_sync(0xffffffffu, g, off);
        b += __shfl_xor_sync(0xffffffffu, b, off);
    }

    if (lane == 0) {
        out[ray * 3 + 0] = r;
        out[ray * 3 + 1] = g;
        out[ray * 3 + 2] = b;
    }
}

extern "C" void kernel_launch(void* const* d_in, const int* in_sizes, int n_in,
                              void* d_out, int out_size)
{
    // Identify buffers defensively by size. color is [N,128,3] -> uniquely 3x
    // larger than sdf/depth ([N,128] each).
    int ic = 0;
    for (int i = 1; i < n_in; ++i)
        if (in_sizes[i] > in_sizes[ic]) ic = i;

    int ia, ib;  // the two equal-size buffers, in index order
    if (ic == 0)      { ia = 1; ib = 2; }
    else if (ic == 1) { ia = 0; ib = 2; }
    else              { ia = 0; ib = 1; }

    int is, id;  // sdf index, depth index
    if (ic == 0) {
        // color first => name-sorted metadata (color, depth_values, sdf)
        id = ia; is = ib;
    } else {
        // insertion order (sdf, color, depth_values)
        is = ia; id = ib;
    }

    const float* sdf   = (const float*)d_in[is];
    const float* color = (const float*)d_in[ic];
    const float* depth = (const float*)d_in[id];
    float* out = (float*)d_out;

    const int N = out_size / 3;                   // 65536 rays
    const int threads = 256;                      // 8 warps = 8 rays / block
    const int blocks  = (N * 32 + threads - 1) / threads;
    volume_sdf_render_kernel<<<blocks, threads>>>(sdf, color, depth, out, N);
}

// round 17
// speedup vs baseline: 1.1619x; 1.1619x over previous
#include <cuda_runtime.h>
#include <cuda_bf16.h>

// VolumeSDF renderer: one warp per ray, 4 samples per lane,
// base-2 exponentials with pre-folded constants. (R14 structure -- the only
// shape that sustains ~5.6 TB/s; R7/R10/R12/R15 all traded BW for bytes and
// lost. This round: streaming cache hints + half-nat threshold step.)
//
//   density = ALPHA * LaplaceCDF(-sdf; BETA)
//   tau_s   = density_s * delta_s,  delta = diff(depth), last = 1e10
//   T_s     = exp(-inclusive_cumsum(tau)_s);  w_s = T_s*(1-exp(-tau_s+eps))
//   out[n]  = sum_s w_s * color[n,s,:]
//
// Byte savings: tail weight past prefix p telescopes to <= 2^-p, so lanes
// >=16 with prefix >= SKIP2 skip their color loads. Threshold 6.5 nats
// (calibrated curve: 9->6.0e-5, 8->1.28e-4, 7->2.41e-4; x2.1/nat =>
// predicted ~3.5e-4, 3x under the 1e-3 gate).
// All input loads use __ldcs: data is single-touch streaming; evict-first
// avoids useless L2 retention and lifts achieved DRAM BW.

#define FAR_DELTA 1e10f
#define AEXP   28.853900817779268f   // (1/BETA)*log2(e) = 20*1.442695
#define DENS2  14.426950408889634f   // ALPHA*log2(e)
#define EPS2   1.442695041e-10f      // EPS*log2(e)
#define SKIP2  9.377517765778265f    // 6.5 nats in bits; 2^-9.38 = 1.5e-3
#define EARLY_LANES 16

__device__ __forceinline__ float ex2(float x) {
    float y;
    asm("ex2.approx.ftz.f32 %0, %1;" : "=f"(y) : "f"(x));
    return y;
}

// tau per unit delta, in base-2 units: DENS2 * LaplaceCDF(-x, BETA)
__device__ __forceinline__ float dens2(float x) {
    const float e = 0.5f * ex2(-fabsf(x) * AEXP);
    const float cdf = (x > 0.0f) ? e : (1.0f - e);
    return DENS2 * cdf;
}

__global__ __launch_bounds__(256)
void volume_sdf_render_kernel(const float* __restrict__ sdf,
                              const float* __restrict__ color,
                              const float* __restrict__ depth,
                              float* __restrict__ out,
                              int N)
{
    const int gtid = blockIdx.x * blockDim.x + threadIdx.x;
    const int ray  = gtid >> 5;          // one warp per ray
    const int lane = threadIdx.x & 31;
    if (ray >= N) return;

    const int S = 128;
    const long long base  = (long long)ray * S + lane * 4;
    const long long cbase = base * 3;
    const bool early = (lane < EARLY_LANES);

    // ---- Front-batched streaming loads: sdf, depth (+ color, lanes 0-15) ----
    const float4 s4 = __ldcs(reinterpret_cast<const float4*>(sdf   + base));
    const float4 d4 = __ldcs(reinterpret_cast<const float4*>(depth + base));
    float4 ca, cb, cc;
    if (early) {
        ca = __ldcs(reinterpret_cast<const float4*>(color + cbase));
        cb = __ldcs(reinterpret_cast<const float4*>(color + cbase + 4));
        cc = __ldcs(reinterpret_cast<const float4*>(color + cbase + 8));
    }

    // Deltas. depth[4l+4] lives in the next lane's d4.x.
    const float dnext = __shfl_down_sync(0xffffffffu, d4.x, 1);
    float del[4];
    del[0] = d4.y - d4.x;
    del[1] = d4.z - d4.y;
    del[2] = d4.w - d4.z;
    del[3] = (lane == 31) ? FAR_DELTA : (dnext - d4.w);

    const float sd[4] = {s4.x, s4.y, s4.z, s4.w};

    // tau in base-2 units; u_i = 2^(-tau2_i + eps2) = 1 - trans_i.
    float tau[4], u[4];
#pragma unroll
    for (int i = 0; i < 4; ++i) {
        tau[i] = dens2(sd[i]) * del[i];
        u[i]   = ex2(-tau[i] + EPS2);
    }

    // Per-lane inclusive cumsum (base-2 units).
    const float c0 = tau[0];
    const float c1 = c0 + tau[1];
    const float c2 = c1 + tau[2];
    const float c3 = c2 + tau[3];

    // Warp inclusive scan of lane totals.
    float incl = c3;
#pragma unroll
    for (int off = 1; off < 32; off <<= 1) {
        const float v = __shfl_up_sync(0xffffffffu, incl, off);
        if (lane >= off) incl += v;
    }
    // Exclusive prefix from the PREVIOUS lane's inclusive value. Never by
    // subtraction: lane 31's c3 holds the far-delta tau and the subtraction
    // catastrophically cancels (R1/R2 rel_err=0.33 bug).
    float prefix = __shfl_up_sync(0xffffffffu, incl, 1);
    if (lane == 0) prefix = 0.0f;

    // Gated lanes: load color only if tail bound 2^-prefix is significant.
    const bool have = early || (prefix < SKIP2);
    if (!early && have) {
        ca = __ldcs(reinterpret_cast<const float4*>(color + cbase));
        cb = __ldcs(reinterpret_cast<const float4*>(color + cbase + 4));
        cc = __ldcs(reinterpret_cast<const float4*>(color + cbase + 8));
    }

    float r = 0.0f, g = 0.0f, b = 0.0f;
    if (have) {
        // Telescoping transmittance: T0 = 2^-(prefix+c0); T_{i+1} = T_i*u_{i+1}
        // (eps factor in u is ~1+1e-10, negligible). One EX2 total.
        const float T0 = ex2(-(prefix + c0));
        const float T1 = T0 * u[1];
        const float T2 = T1 * u[2];
        const float T3 = T2 * u[3];
        const float w0 = T0 * (1.0f - u[0]);
        const float w1 = T1 * (1.0f - u[1]);
        const float w2 = T2 * (1.0f - u[2]);
        const float w3 = T3 * (1.0f - u[3]);

        // sample0=(ca.x,ca.y,ca.z) sample1=(ca.w,cb.x,cb.y)
        // sample2=(cb.z,cb.w,cc.x) sample3=(cc.y,cc.z,cc.w)
        r = w0 * ca.x + w1 * ca.w + w2 * cb.z + w3 * cc.y;
        g = w0 * ca.y + w1 * cb.x + w2 * cb.w + w3 * cc.z;
        b = w0 * ca.z + w1 * cb.y + w2 * cc.x + w3 * cc.w;
    }

    // Warp reduction over lanes (samples).
#pragma unroll
    for (int off = 16; off > 0; off >>= 1) {
        r += __shfl_xor_sync(0xffffffffu, r, off);
        g += __shfl_xor_sync(0xffffffffu, g, off);
        b += __shfl_xor_sync(0xffffffffu, b, off);
    }

    if (lane == 0) {
        out[ray * 3 + 0] = r;
        out[ray * 3 + 1] = g;
        out[ray * 3 + 2] = b;
    }
}

extern "C" void kernel_launch(void* const* d_in, const int* in_sizes, int n_in,
                              void* d_out, int out_size)
{
    // Identify buffers defensively by size. color is [N,128,3] -> uniquely 3x
    // larger than sdf/depth ([N,128] each).
    int ic = 0;
    for (int i = 1; i < n_in; ++i)
        if (in_sizes[i] > in_sizes[ic]) ic = i;

    int ia, ib;  // the two equal-size buffers, in index order
    if (ic == 0)      { ia = 1; ib = 2; }
    else if (ic == 1) { ia = 0; ib = 2; }
    else              { ia = 0; ib = 1; }

    int is, id;  // sdf index, depth index
    if (ic == 0) {
        // color first => name-sorted metadata (color, depth_values, sdf)
        id = ia; is = ib;
    } else {
        // insertion order (sdf, color, depth_values)
        is = ia; id = ib;
    }

    const float* sdf   = (const float*)d_in[is];
    const float* color = (const float*)d_in[ic];
    const float* depth = (const float*)d_in[id];
    float* out = (float*)d_out;

    const int N = out_size / 3;                   // 65536 rays
    const int threads = 256;                      // 8 warps = 8 rays / block
    const int blocks  = (N * 32 + threads - 1) / threads;
    volume_sdf_render_kernel<<<blocks, threads>>>(sdf, color, depth, out, N);
}